// round 4
// baseline (speedup 1.0000x reference)
#include <cuda_runtime.h>
#include <cuda_bf16.h>
#include <cstdint>

#define NUM_EMB 32
#define ADIM 32
#define HID 1024
#define BB 128
#define TT 64
#define ROWS_TOTAL (BB*TT)   /* 8192 grouped rows */

// ---------------- scratch (device globals; no allocs allowed) ----------------
__device__ float g_aemb[(ROWS_TOTAL + 128) * HID];   // grouped a_emb (tf32-rounded), +pad rows
__device__ float g_h   [(ROWS_TOTAL + 128) * HID];   // grouped hidden (tf32-rounded), +pad rows
__device__ float g_tau [BB * HID];                   // grouped tau
__device__ float g_t2  [BB * HID];                   // grouped tau@W2b + b2
__device__ int   g_batch_of_pos[BB];
__device__ int   g_seg_start[NUM_EMB + 1];
__device__ int   g_mb_cat[128], g_mb_row[128], g_mb_rows[128];
__device__ int   g_mb_count;

// ---------------- helpers ----------------
__device__ __forceinline__ unsigned tf32r_bits(float x) {
    unsigned r;
    asm("cvt.rna.tf32.f32 %0, %1;" : "=r"(r) : "f"(x));
    return r;
}
__device__ __forceinline__ float tf32r(float x) {
    return __uint_as_float(tf32r_bits(x));
}
__device__ __forceinline__ void cpasync16(void* dst, const void* src) {
    unsigned s = (unsigned)__cvta_generic_to_shared(dst);
    asm volatile("cp.async.cg.shared.global [%0], [%1], 16;" :: "r"(s), "l"(src));
}
__device__ __forceinline__ void mma_tf32(float c[4], const unsigned a[4], const unsigned b[2]) {
    asm volatile(
        "mma.sync.aligned.m16n8k8.row.col.f32.tf32.tf32.f32 "
        "{%0,%1,%2,%3}, {%4,%5,%6,%7}, {%8,%9}, {%0,%1,%2,%3};"
        : "+f"(c[0]), "+f"(c[1]), "+f"(c[2]), "+f"(c[3])
        : "r"(a[0]), "r"(a[1]), "r"(a[2]), "r"(a[3]), "r"(b[0]), "r"(b[1]));
}

// ---------------- kernel 0: category grouping + mblock table ----------------
__global__ void setup_kernel(const int* __restrict__ cats) {
    if (threadIdx.x != 0) return;
    int cnt[NUM_EMB];
    for (int c = 0; c < NUM_EMB; c++) cnt[c] = 0;
    for (int b = 0; b < BB; b++) cnt[cats[b]]++;
    int s = 0;
    for (int c = 0; c < NUM_EMB; c++) { g_seg_start[c] = s; s += cnt[c]; }
    g_seg_start[NUM_EMB] = s;
    int cur[NUM_EMB];
    for (int c = 0; c < NUM_EMB; c++) cur[c] = g_seg_start[c];
    for (int b = 0; b < BB; b++) {
        int c = cats[b];
        int p = cur[c]++;
        g_batch_of_pos[p] = b;
    }
    int nmb = 0;
    for (int c = 0; c < NUM_EMB; c++) {
        int rows = cnt[c] * TT;
        int r0 = g_seg_start[c] * TT;
        for (int r = 0; r < rows; r += 128) {
            g_mb_cat[nmb] = c;
            g_mb_row[nmb] = r0 + r;
            g_mb_rows[nmb] = (rows - r < 128) ? (rows - r) : 128;
            nmb++;
        }
    }
    g_mb_count = nmb;
}

// ---------------- kernel 1: tau (fp64 trig, grouped layout) ----------------
__global__ void tau_kernel(const float* __restrict__ ts) {
    int pos = blockIdx.x;
    int j = threadIdx.x;               // 0..511
    int b = g_batch_of_pos[pos];
    double t = (double)ts[b];
    double f = exp(-9.210340371976184 * ((double)j) / 512.0);
    double ph = t * f;
    g_tau[pos * HID + j]       = (float)sin(ph);
    g_tau[pos * HID + 512 + j] = (float)cos(ph);
}

// ---------------- kernel 2: a_emb = actions @ W1 + b1 (grouped, tf32-rounded) ----------------
__global__ void aemb_kernel(const float* __restrict__ actions,
                            const float* __restrict__ W1w,
                            const float* __restrict__ W1b,
                            const int*   __restrict__ cats) {
    __shared__ float As[TT * ADIM];
    int pos = blockIdx.x;
    int tid = threadIdx.x;             // 256 threads
    int b = g_batch_of_pos[pos];
    int c = cats[b];
    for (int i = tid; i < TT * ADIM; i += 256)
        As[i] = actions[b * TT * ADIM + i];
    __syncthreads();
    const float* W = W1w + (size_t)c * ADIM * HID;
    const float* bias = W1b + (size_t)c * HID;
    for (int j = 0; j < 4; j++) {
        int n = tid + j * 256;
        float w[ADIM];
#pragma unroll
        for (int k = 0; k < ADIM; k++) w[k] = W[(size_t)k * HID + n];
        float bn = bias[n];
        for (int m = 0; m < TT; m++) {
            float acc = bn;
#pragma unroll
            for (int k = 0; k < ADIM; k++) acc += As[m * ADIM + k] * w[k];
            g_aemb[(size_t)(pos * TT + m) * HID + n] = tf32r(acc);
        }
    }
}

// ---------------- kernel 3: t2 = tau @ W2[1024:2048] + b2 (per category) ----------------
// grid (32 cats, 8 n-tiles), 512 threads = 4 k-slices x 128 n-lanes
__global__ void t2_kernel(const float* __restrict__ W2w,
                          const float* __restrict__ W2bias) {
    __shared__ float tauS[8][HID];      // 32 KB
    __shared__ float red[4][8][128];    // 16 KB
    int c = blockIdx.x, nt = blockIdx.y;
    int lane127 = threadIdx.x & 127;
    int kg = threadIdx.x >> 7;          // 0..3
    int n = nt * 128 + lane127;
    int s0 = g_seg_start[c], s1 = g_seg_start[c + 1];
    const float* Wb = W2w + ((size_t)c * 2048 + 1024) * HID;
    for (int p0 = s0; p0 < s1; p0 += 8) {
        int pc = s1 - p0; if (pc > 8) pc = 8;
        for (int i = threadIdx.x; i < 8 * HID; i += 512)
            tauS[i >> 10][i & 1023] =
                (i < pc * HID) ? g_tau[(size_t)(p0 + (i >> 10)) * HID + (i & 1023)] : 0.f;
        __syncthreads();
        float acc[8];
#pragma unroll
        for (int q = 0; q < 8; q++) acc[q] = 0.f;
        int kbeg = kg * 256;
        for (int k = kbeg; k < kbeg + 256; k += 8) {
            float w[8];
#pragma unroll
            for (int i = 0; i < 8; i++) w[i] = Wb[(size_t)(k + i) * HID + n];
#pragma unroll
            for (int i = 0; i < 8; i++)
#pragma unroll
                for (int q = 0; q < 8; q++) acc[q] += tauS[q][k + i] * w[i];
        }
#pragma unroll
        for (int q = 0; q < 8; q++) red[kg][q][lane127] = acc[q];
        __syncthreads();
        if (kg == 0) {
            float bv = W2bias[(size_t)c * HID + n];
            for (int q = 0; q < pc; q++) {
                float v = red[0][q][lane127] + red[1][q][lane127] +
                          red[2][q][lane127] + red[3][q][lane127] + bv;
                g_t2[(size_t)(p0 + q) * HID + n] = v;
            }
        }
        __syncthreads();
    }
}

// ---------------- kernels 4/5: grouped tf32 GEMM (BM=128, BN=128, KC=16) ----------------
// GEMM2: A=g_aemb (pre-rounded tf32), B=W2w rows[0:1024], epi: +t2, silu, -> g_h (tf32)
// GEMM3: A=g_h,                        B=W3w,             epi: +b3, scatter -> out
// NOTE: A operand is selected INSIDE device code (g_aemb / g_h device globals).
// Passing these as host-side kernel arguments is invalid (host shadow address;
// with GB300 ATS it silently reads host memory) — that was the round-2 bug.
template<bool GEMM2>
__global__ __launch_bounds__(256, 2)
void gemm_kernel(const float* __restrict__ Bbase,
                 size_t cat_stride,
                 const float* __restrict__ bias3,
                 float* __restrict__ out) {
    int mb = blockIdx.x;
    if (mb >= g_mb_count) return;
    const float* Ag = GEMM2 ? g_aemb : g_h;   // device-side symbol address (correct)
    int c = g_mb_cat[mb], mrow0 = g_mb_row[mb], m_rows = g_mb_rows[mb];
    int n0 = blockIdx.y * 128;
    const float* Bg = Bbase + (size_t)c * cat_stride;

    __shared__ float As[2][128 * 20];   // row-major, stride 20 floats (conflict-free frags)
    __shared__ float Bs[2][16 * 136];   // k-major, stride 136 floats (conflict-free frags)

    int tid = threadIdx.x, lane = tid & 31, wid = tid >> 5;
    int wm = wid >> 2, wn = wid & 3;    // 2 x 4 warp grid, warp tile 64x32
    int g = lane >> 2, tg = lane & 3;

    float acc[4][4][4];
#pragma unroll
    for (int a = 0; a < 4; a++)
#pragma unroll
        for (int b = 0; b < 4; b++)
#pragma unroll
            for (int i = 0; i < 4; i++) acc[a][b][i] = 0.f;

    auto load_stage = [&](int kt, int buf) {
        int k0 = kt * 16;
#pragma unroll
        for (int i = 0; i < 2; i++) {           // A: 512 x 16B chunks
            int q = tid + i * 256;
            int row = q >> 2, c4 = (q & 3) * 4;
            cpasync16(&As[buf][row * 20 + c4],
                      Ag + (size_t)(mrow0 + row) * HID + k0 + c4);
        }
#pragma unroll
        for (int i = 0; i < 2; i++) {           // B: 512 x 16B chunks
            int q = tid + i * 256;
            int kk = q >> 5, c4 = (q & 31) * 4;
            cpasync16(&Bs[buf][kk * 136 + c4],
                      Bg + (size_t)(k0 + kk) * HID + n0 + c4);
        }
    };

    load_stage(0, 0);
    asm volatile("cp.async.commit_group;");
    int buf = 0;
    for (int kt = 0; kt < 64; kt++) {
        if (kt + 1 < 64) {
            load_stage(kt + 1, buf ^ 1);
            asm volatile("cp.async.commit_group;");
            asm volatile("cp.async.wait_group 1;");
        } else {
            asm volatile("cp.async.wait_group 0;");
        }
        __syncthreads();
#pragma unroll
        for (int ks = 0; ks < 2; ks++) {
            int kb = ks * 8;
            unsigned af[4][4];
#pragma unroll
            for (int fm = 0; fm < 4; fm++) {
                const float* ap = &As[buf][(wm * 64 + fm * 16 + g) * 20 + kb + tg];
                af[fm][0] = __float_as_uint(ap[0]);
                af[fm][1] = __float_as_uint(ap[8 * 20]);
                af[fm][2] = __float_as_uint(ap[4]);
                af[fm][3] = __float_as_uint(ap[8 * 20 + 4]);
            }
            unsigned bfr[4][2];
#pragma unroll
            for (int fn = 0; fn < 4; fn++) {
                const float* bp = &Bs[buf][(kb + tg) * 136 + wn * 32 + fn * 8 + g];
                bfr[fn][0] = tf32r_bits(bp[0]);
                bfr[fn][1] = tf32r_bits(bp[4 * 136]);
            }
#pragma unroll
            for (int fm = 0; fm < 4; fm++)
#pragma unroll
                for (int fn = 0; fn < 4; fn++)
                    mma_tf32(acc[fm][fn], af[fm], bfr[fn]);
        }
        __syncthreads();
        buf ^= 1;
    }

    // epilogue
#pragma unroll
    for (int fm = 0; fm < 4; fm++)
#pragma unroll
        for (int fn = 0; fn < 4; fn++)
#pragma unroll
            for (int i = 0; i < 4; i++) {
                int row = wm * 64 + fm * 16 + g + ((i & 2) ? 8 : 0);
                if (row >= m_rows) continue;
                int col = n0 + wn * 32 + fn * 8 + tg * 2 + (i & 1);
                int R = mrow0 + row;
                float v = acc[fm][fn][i];
                if (GEMM2) {
                    v += g_t2[(size_t)(R >> 6) * HID + col];
                    v = v / (1.f + expf(-v));                 // silu
                    g_h[(size_t)R * HID + col] = tf32r(v);
                } else {
                    v += bias3[(size_t)c * HID + col];
                    int b = g_batch_of_pos[R >> 6];
                    out[((size_t)b * TT + (R & 63)) * HID + col] = v;
                }
            }
}

// ---------------- launch ----------------
extern "C" void kernel_launch(void* const* d_in, const int* in_sizes, int n_in,
                              void* d_out, int out_size) {
    const float* actions   = (const float*)d_in[0];
    const float* timesteps = (const float*)d_in[1];
    const float* W1w       = (const float*)d_in[2];
    const float* W1b       = (const float*)d_in[3];
    const float* W2w       = (const float*)d_in[4];
    const float* W2b       = (const float*)d_in[5];
    const float* W3w       = (const float*)d_in[6];
    const float* W3b       = (const float*)d_in[7];
    const int*   cats      = (const int*)d_in[8];
    float* out = (float*)d_out;

    setup_kernel<<<1, 32>>>(cats);
    tau_kernel<<<BB, 512>>>(timesteps);
    aemb_kernel<<<BB, 256>>>(actions, W1w, W1b, cats);
    t2_kernel<<<dim3(NUM_EMB, 8), 512>>>(W2w, W2b);
    gemm_kernel<true><<<dim3(96, 8), 256>>>(W2w, (size_t)2048 * HID, nullptr, nullptr);
    gemm_kernel<false><<<dim3(96, 8), 256>>>(W3w, (size_t)HID * HID, W3b, out);
}